// round 2
// baseline (speedup 1.0000x reference)
#include <cuda_runtime.h>

// Problem constants
#define BB   32
#define HW_  1600
#define A_   5
#define NGT  128
#define CC   80

constexpr int NPRED       = BB * HW_ * A_;            // 256000
constexpr int IOUS_OFF    = NPRED * 4;                // ious_t   (1,024,000)
constexpr int CLASSES_OFF = IOUS_OFF + NPRED;         // classes  (1,280,000)
constexpr int BOXM_OFF    = CLASSES_OFF + NPRED * CC; // box_mask (21,760,000)
constexpr int IOUM_OFF    = BOXM_OFF + NPRED;         // iou_mask (22,016,000)
constexpr int CLSM_OFF    = IOUM_OFF + NPRED;         // class_mask (22,272,000)

// ---------------------------------------------------------------------------
// Kernel 1: fused defaults-fill + noobject iou_mask.
// One thread per pred box. 160 threads/block => 50 blocks per batch; each
// block caches its batch's FULL 128 gt boxes in shared memory.
//
// KEY: the reference's best-IoU max runs over ALL 128 gt rows (num_boxes only
// gates the scatter), so the loop below is over NGT, not num_boxes.
//
// Division-free threshold: iou >= 0.6  <=>  inter >= 0.375*(barea+garea),
// with "+1" folded into x2+1/y2+1 (min/max commute with the monotone +1).
// ---------------------------------------------------------------------------
__global__ void __launch_bounds__(160) yolo_main_kernel(
    const float4* __restrict__ bbox_pred,   // NPRED float4
    const float*  __restrict__ iou_pred,    // NPRED
    const float*  __restrict__ gt,          // BB * NGT * 5
    const float*  __restrict__ anchors,     // 5*2
    float*        __restrict__ out)
{
    __shared__ float4 g4[NGT];   // x1, y1, x2+1, y2+1
    __shared__ float  sg[NGT];   // 0.375 * garea

    const int t = blockIdx.x * 160 + threadIdx.x;
    const int b = t / (HW_ * A_);

    if (threadIdx.x < NGT) {
        const float* p = gt + ((long)b * NGT + threadIdx.x) * 5;
        float x1 = p[0], y1 = p[1], x2 = p[2], y2 = p[3];
        g4[threadIdx.x] = make_float4(x1, y1, x2 + 1.0f, y2 + 1.0f);
        sg[threadIdx.x] = 0.375f * (x2 - x1 + 1.0f) * (y2 - y1 + 1.0f);
    }
    __syncthreads();

    // ---- default fills ----
    float4* out4 = (float4*)out;
    out4[t] = make_float4(0.5f, 0.5f, 1.0f, 1.0f);     // boxes_t default
    out[IOUS_OFF + t] = 0.0f;                          // ious_t
    out[BOXM_OFF + t] = 0.01f;                         // box_mask
    out[CLSM_OFF + t] = 0.0f;                          // class_mask

    // classes = 0, warp-coalesced: each warp zeroes its contiguous 32*80 floats
    {
        const int lane = threadIdx.x & 31;
        const long cbase = (long)(CLASSES_OFF / 4) + (long)(t >> 5) * (32 * 20);
        const float4 z = make_float4(0.f, 0.f, 0.f, 0.f);
        #pragma unroll
        for (int i = 0; i < 20; i++)
            out4[cbase + (long)i * 32 + lane] = z;
    }

    // ---- this thread's pred box in pixel coords ----
    const int hw = (t / A_) % HW_;
    const int a  = t % A_;
    const float4 bp = bbox_pred[t];
    const float col = (float)(hw % 40);
    const float row = (float)(hw / 40);
    const float cxp = (bp.x + col) * (1.0f / 40.0f);
    const float cyp = (bp.y + row) * (1.0f / 40.0f);
    const float bw  = bp.z * anchors[2 * a]     * (1.0f / 40.0f) * 0.5f;
    const float bh  = bp.w * anchors[2 * a + 1] * (1.0f / 40.0f) * 0.5f;
    const float x1  = (cxp - bw) * 1280.0f;
    const float y1  = (cyp - bh) * 1280.0f;
    const float x2p = (cxp + bw) * 1280.0f + 1.0f;
    const float y2p = (cyp + bh) * 1280.0f + 1.0f;
    const float sb  = 0.375f * (x2p - x1) * (y2p - y1);   // 0.375 * barea

    // ---- "any gt (ALL 128) with iou >= 0.6" ----
    bool hit = false;
    #pragma unroll 8
    for (int n = 0; n < NGT; n++) {
        const float4 g = g4[n];
        float iw = fminf(x2p, g.z) - fmaxf(x1, g.x);
        float ih = fminf(y2p, g.w) - fmaxf(y1, g.y);
        iw = fmaxf(iw, 0.0f);
        ih = fmaxf(ih, 0.0f);
        hit = hit | (iw * ih >= sb + sg[n]);
    }

    out[IOUM_OFF + t] = hit ? 0.0f : -iou_pred[t];
}

// ---------------------------------------------------------------------------
// Kernel 2: per-gt-box scatter. One block per batch, one thread per gt box.
// Deterministic last-index-wins dedup (matches sequential .at[].set order).
// classes written for ALL valid boxes (index includes class, no collisions
// across duplicate flat indices with different classes; same (flat,cls) both
// write 1.0 so order is irrelevant).
// ---------------------------------------------------------------------------
__global__ void __launch_bounds__(NGT) yolo_scatter_kernel(
    const float* __restrict__ bbox_pred,
    const float* __restrict__ iou_pred,
    const float* __restrict__ gt,
    const float* __restrict__ anchors,
    const int*   __restrict__ num_boxes,
    float*       __restrict__ out)
{
    const int b = blockIdx.x;
    const int n = threadIdx.x;
    __shared__ int sflat[NGT];

    const float* p = gt + ((long)b * NGT + n) * 5;
    const float x1 = p[0], y1 = p[1], x2 = p[2], y2 = p[3];
    const int cls = (int)p[4];
    const int nb = num_boxes[b];

    const float cx = (x1 + x2) * 0.5f / 32.0f;
    const float cy = (y1 + y2) * 0.5f / 32.0f;
    const float fcx = floorf(cx);
    const float fcy = floorf(cy);
    const int cell = (int)(fcy * 40.0f + fcx);
    const bool valid = (n < nb) && (cell >= 0) && (cell < HW_);

    // anchor argmax (first max wins, like jnp.argmax)
    const float gw = (x2 / 32.0f - x1 / 32.0f) + 1.0f;
    const float gh = (y2 / 32.0f - y1 / 32.0f) + 1.0f;
    const float gwh = gw * gh;
    int a_ind = 0;
    float bestA = -1.0f;
    #pragma unroll
    for (int a = 0; a < A_; a++) {
        const float aw = anchors[2 * a], ah = anchors[2 * a + 1];
        const float iwa = fminf(aw, gw), iha = fminf(ah, gh);
        const float inta = iwa * iha;
        const float aiou = inta / (aw * ah + gwh - inta);
        if (aiou > bestA) { bestA = aiou; a_ind = a; }
    }

    const int flat = (b * HW_ + cell) * A_ + a_ind;
    sflat[n] = valid ? flat : -1;
    __syncthreads();
    if (!valid) return;

    // classes scatter: all valid gt boxes write
    out[CLASSES_OFF + (long)flat * CC + cls] = 1.0f;

    // last-index-wins dedup for the remaining scatters
    for (int m = n + 1; m < NGT; m++)
        if (sflat[m] == flat) return;

    // tboxes
    const float tw = (x2 - x1 + 1.0f) / 32.0f;
    const float th = (y2 - y1 + 1.0f) / 32.0f;
    const float aw = anchors[2 * a_ind], ah = anchors[2 * a_ind + 1];
    ((float4*)out)[flat] = make_float4(cx - fcx, cy - fcy, tw / aw, th / ah);

    // exact IoU(pred box @flat, this gt) -- mirrors reference formula
    const float* bp = bbox_pred + (long)flat * 4;
    const float colf = (float)(cell % 40);
    const float rowf = (float)(cell / 40);
    const float cxp = (bp[0] + colf) / 40.0f;
    const float cyp = (bp[1] + rowf) / 40.0f;
    const float bw = bp[2] * aw / 40.0f * 0.5f;
    const float bh = bp[3] * ah / 40.0f * 0.5f;
    const float bx1 = (cxp - bw) * 1280.0f;
    const float by1 = (cyp - bh) * 1280.0f;
    const float bx2 = (cxp + bw) * 1280.0f;
    const float by2 = (cyp + bh) * 1280.0f;
    const float barea = (bx2 - bx1 + 1.0f) * (by2 - by1 + 1.0f);
    const float garea = (x2 - x1 + 1.0f) * (y2 - y1 + 1.0f);
    const float iw = fmaxf(fminf(bx2, x2) - fmaxf(bx1, x1) + 1.0f, 0.0f);
    const float ih = fmaxf(fminf(by2, y2) - fmaxf(by1, y1) + 1.0f, 0.0f);
    const float inter = iw * ih;
    const float iou = inter / (barea + garea - inter);

    out[IOUS_OFF + flat] = iou;
    out[BOXM_OFF + flat] = 1.0f;                               // COORD_SCALE
    out[IOUM_OFF + flat] = 5.0f * (1.0f - iou_pred[flat]);     // OBJECT_SCALE
    out[CLSM_OFF + flat] = 1.0f;                               // CLASS_SCALE
}

extern "C" void kernel_launch(void* const* d_in, const int* in_sizes, int n_in,
                              void* d_out, int out_size)
{
    const float4* bbox4   = (const float4*)d_in[0];
    const float*  bbox    = (const float*)d_in[0];
    const float*  ioup    = (const float*)d_in[1];
    const float*  gt      = (const float*)d_in[2];
    const float*  anchors = (const float*)d_in[3];
    const int*    nboxes  = (const int*)d_in[4];
    float* out = (float*)d_out;

    yolo_main_kernel<<<1600, 160>>>(bbox4, ioup, gt, anchors, out);
    yolo_scatter_kernel<<<BB, NGT>>>(bbox, ioup, gt, anchors, nboxes, out);
}

// round 3
// speedup vs baseline: 1.5162x; 1.5162x over previous
#include <cuda_runtime.h>

#define BB   32
#define HW_  1600
#define A_   5
#define NGT  128
#define CC   80
#define TPB  160   // threads per block = pred boxes per block; 50 blocks/batch

constexpr int NPRED       = BB * HW_ * A_;            // 256000
constexpr int IOUS_OFF    = NPRED * 4;
constexpr int CLASSES_OFF = IOUS_OFF + NPRED;
constexpr int BOXM_OFF    = CLASSES_OFF + NPRED * CC;
constexpr int IOUM_OFF    = BOXM_OFF + NPRED;
constexpr int CLSM_OFF    = IOUM_OFF + NPRED;

// ---------------------------------------------------------------------------
// Single fused kernel. One thread per pred box; blocks batch-aligned.
// - gt metadata computed redundantly per block (tid < 128)
// - last-index-wins scatter resolved via smem atomicMax into the OWNING block
// - every output element written exactly once by its owning pred thread,
//   except classes (zero-fill then 1.0-set after a block barrier)
// - noobject test division-free with sb hoisted out of the loop compare
// ---------------------------------------------------------------------------
__global__ void __launch_bounds__(TPB) yolo_fused_kernel(
    const float4* __restrict__ bbox_pred,   // NPRED float4
    const float*  __restrict__ iou_pred,    // NPRED
    const float*  __restrict__ gt,          // BB * NGT * 5
    const float*  __restrict__ anchors,     // 5*2
    const int*    __restrict__ num_boxes,   // BB
    float*        __restrict__ out)
{
    __shared__ float4 g4[NGT];     // x1, y1, x2+1, y2+1
    __shared__ float  sg[NGT];     // 0.375 * garea
    __shared__ float  sga[NGT];    // garea
    __shared__ float4 stbox[NGT];  // target tbox per gt
    __shared__ int    swin[TPB];   // winning gt index per local pred slot

    const int tid = threadIdx.x;
    const int t0  = blockIdx.x * TPB;
    const int t   = t0 + tid;
    const int b   = blockIdx.x / 50;

    swin[tid] = -1;

    // ---- phase A: gt metadata (tid < 128) ----
    int  my_flat = 0, my_local = -1, my_cls = 0;
    bool my_valid = false;
    if (tid < NGT) {
        const float* p = gt + ((long)b * NGT + tid) * 5;
        const float x1 = p[0], y1 = p[1], x2 = p[2], y2 = p[3];
        my_cls = (int)p[4];
        g4[tid] = make_float4(x1, y1, x2 + 1.0f, y2 + 1.0f);
        const float ga = (x2 - x1 + 1.0f) * (y2 - y1 + 1.0f);
        sga[tid] = ga;
        sg[tid]  = 0.375f * ga;

        const float cx = (x1 + x2) * 0.5f / 32.0f;
        const float cy = (y1 + y2) * 0.5f / 32.0f;
        const float fcx = floorf(cx), fcy = floorf(cy);
        const int cell = (int)(fcy * 40.0f + fcx);
        const int nb = num_boxes[b];
        my_valid = (tid < nb) && (cell >= 0) && (cell < HW_);

        // anchor argmax (first max wins)
        const float gw = (x2 / 32.0f - x1 / 32.0f) + 1.0f;
        const float gh = (y2 / 32.0f - y1 / 32.0f) + 1.0f;
        const float gwh = gw * gh;
        int a_ind = 0;
        float bestA = -1.0f;
        #pragma unroll
        for (int a = 0; a < A_; a++) {
            const float aw = anchors[2 * a], ah = anchors[2 * a + 1];
            const float inta = fminf(aw, gw) * fminf(ah, gh);
            const float aiou = inta / (aw * ah + gwh - inta);
            if (aiou > bestA) { bestA = aiou; a_ind = a; }
        }

        my_flat  = (b * HW_ + cell) * A_ + a_ind;
        my_local = my_flat - t0;
        const float tw = (x2 - x1 + 1.0f) / 32.0f;
        const float th = (y2 - y1 + 1.0f) / 32.0f;
        stbox[tid] = make_float4(cx - fcx, cy - fcy,
                                 tw / anchors[2 * a_ind],
                                 th / anchors[2 * a_ind + 1]);
    }
    __syncthreads();

    // ---- phase B: scatter ownership (last index wins -> max n) ----
    if (tid < NGT && my_valid && my_local >= 0 && my_local < TPB)
        atomicMax(&swin[my_local], tid);
    __syncthreads();

    // ---- phase C: per-pred-box work ----
    const int hw = (t / A_) % HW_;
    const int a  = t % A_;
    const float4 bp = bbox_pred[t];
    const float ip  = iou_pred[t];
    const float col = (float)(hw % 40);
    const float row = (float)(hw / 40);
    const float cxp = (bp.x + col) * (1.0f / 40.0f);
    const float cyp = (bp.y + row) * (1.0f / 40.0f);
    const float bw  = bp.z * anchors[2 * a]     * (1.0f / 40.0f) * 0.5f;
    const float bh  = bp.w * anchors[2 * a + 1] * (1.0f / 40.0f) * 0.5f;
    const float x1  = (cxp - bw) * 1280.0f;
    const float y1  = (cyp - bh) * 1280.0f;
    const float x2p = (cxp + bw) * 1280.0f + 1.0f;
    const float y2p = (cyp + bh) * 1280.0f + 1.0f;
    const float sb  = 0.375f * (x2p - x1) * (y2p - y1);

    // any gt (ALL 128) with iou >= 0.6:  max_n(iw*ih - sg[n]) >= sb
    // iw clamped >= 0 so ih<0 => product <= 0 < sb (no false positive).
    float acc = -1e30f;
    #pragma unroll 16
    for (int n = 0; n < NGT; n++) {
        const float4 g = g4[n];
        float iw = fminf(x2p, g.z) - fmaxf(x1, g.x);
        const float ih = fminf(y2p, g.w) - fmaxf(y1, g.y);
        iw = fmaxf(iw, 0.0f);
        acc = fmaxf(acc, fmaf(iw, ih, -sg[n]));
    }
    const bool hit = (acc >= sb);

    float4* out4 = (float4*)out;
    const int win = swin[tid];
    if (win >= 0) {
        // matched slot: exact IoU vs the winning gt
        const float4 g = g4[win];
        const float iw = fmaxf(fminf(x2p, g.z) - fmaxf(x1, g.x), 0.0f);
        const float ih = fmaxf(fminf(y2p, g.w) - fmaxf(y1, g.y), 0.0f);
        const float inter = iw * ih;
        const float ba = (x2p - x1) * (y2p - y1);
        const float iou = inter / (ba + sga[win] - inter);
        out4[t] = stbox[win];
        out[IOUS_OFF + t] = iou;
        out[BOXM_OFF + t] = 1.0f;
        out[IOUM_OFF + t] = 5.0f * (1.0f - ip);
        out[CLSM_OFF + t] = 1.0f;
    } else {
        out4[t] = make_float4(0.5f, 0.5f, 1.0f, 1.0f);
        out[IOUS_OFF + t] = 0.0f;
        out[BOXM_OFF + t] = 0.01f;
        out[IOUM_OFF + t] = hit ? 0.0f : -ip;
        out[CLSM_OFF + t] = 0.0f;
    }

    // classes = 0, warp-coalesced (each warp zeroes its own 32 threads' rows)
    {
        const int lane = tid & 31;
        const long cbase = (long)(CLASSES_OFF / 4) + (long)(t >> 5) * (32 * 20);
        const float4 z = make_float4(0.f, 0.f, 0.f, 0.f);
        #pragma unroll
        for (int i = 0; i < 20; i++)
            out4[cbase + (long)i * 32 + lane] = z;
    }

    // ---- phase D: classes 1.0-set (after zero-fill of this block's rows) ----
    __syncthreads();
    if (tid < NGT && my_valid && my_local >= 0 && my_local < TPB)
        out[CLASSES_OFF + (long)my_flat * CC + my_cls] = 1.0f;
}

extern "C" void kernel_launch(void* const* d_in, const int* in_sizes, int n_in,
                              void* d_out, int out_size)
{
    const float4* bbox4   = (const float4*)d_in[0];
    const float*  ioup    = (const float*)d_in[1];
    const float*  gtb     = (const float*)d_in[2];
    const float*  anchors = (const float*)d_in[3];
    const int*    nboxes  = (const int*)d_in[4];
    float* out = (float*)d_out;

    yolo_fused_kernel<<<NPRED / TPB, TPB>>>(bbox4, ioup, gtb, anchors, nboxes, out);
}